// round 14
// baseline (speedup 1.0000x reference)
#include <cuda_runtime.h>
#include <cuda_bf16.h>
#include <cstdint>

#define NN   65536
#define SS   128
#define DIN  512
#define HH   1024
#define DOUTT 256

// ---------------- static device scratch ----------------
__device__ float g_u[NN];
__device__ float g_v2[HH];
__device__ float g_c;
__device__ float g_gram_part[512 * 128 * 128];   // 512 partial Gram matrices
__device__ float g_y_part[512 * 128];
__device__ float g_G[128 * 128];
__device__ float g_y[128];
__device__ float g_wprime[128];
// bf16 hi/lo scratch: d1 written by k_mlp itself (nc==0), W1 pre-split
__device__ __nv_bfloat16 g_d1hi[(size_t)NN * DIN];
__device__ __nv_bfloat16 g_d1lo[(size_t)NN * DIN];
__device__ __nv_bfloat16 g_w1hiT[(size_t)HH * DIN];  // [n][k]
__device__ __nv_bfloat16 g_w1loT[(size_t)HH * DIN];

// ---------------- helpers (baseline PTX only — must compile for plain sm_103) ----------------
__device__ __forceinline__ uint32_t smem_u32(const void* p) {
    uint32_t a;
    asm("{ .reg .u64 t; cvta.to.shared.u64 t, %1; cvt.u32.u64 %0, t; }" : "=r"(a) : "l"(p));
    return a;
}
__device__ __forceinline__ void cp16(uint32_t dst, const void* src) {
    asm volatile("cp.async.cg.shared.global [%0], [%1], 16;" :: "r"(dst), "l"(src));
}
#define CP_COMMIT() asm volatile("cp.async.commit_group;" ::: "memory")
#define CP_WAIT0()  asm volatile("cp.async.wait_group 0;" ::: "memory")

__device__ __forceinline__ void mma_bf16(float* c, const uint32_t* a, const uint32_t* b) {
    asm volatile("mma.sync.aligned.m16n8k16.row.col.f32.bf16.bf16.f32 "
        "{%0,%1,%2,%3}, {%4,%5,%6,%7}, {%8,%9}, {%0,%1,%2,%3};"
        : "+f"(c[0]), "+f"(c[1]), "+f"(c[2]), "+f"(c[3])
        : "r"(a[0]), "r"(a[1]), "r"(a[2]), "r"(a[3]), "r"(b[0]), "r"(b[1]));
}
__device__ __forceinline__ void ldm_x4(uint32_t* r, uint32_t addr) {
    asm volatile("ldmatrix.sync.aligned.m8n8.x4.shared.b16 {%0,%1,%2,%3}, [%4];"
        : "=r"(r[0]), "=r"(r[1]), "=r"(r[2]), "=r"(r[3]) : "r"(addr));
}
// pack two fp32 -> bf16x2 word, round-nearest; low half = second operand
__device__ __forceinline__ uint32_t cvt2(float hi, float lo) {
    uint32_t r;
    asm("cvt.rn.bf16x2.f32 %0, %1, %2;" : "=r"(r) : "f"(hi), "f"(lo));
    return r;
}

// ---------------- K0: split W1 -> transposed bf16 hi/lo [n][k] ----------------
__global__ void k_split_w1(const float* __restrict__ W1) {
    __shared__ float t[32][33];
    const int tx = threadIdx.x, ty = threadIdx.y;       // 32 x 8
    const int n0 = blockIdx.x * 32, k0 = blockIdx.y * 32;
#pragma unroll
    for (int i = 0; i < 4; i++)
        t[ty + i * 8][tx] = W1[(size_t)(k0 + ty + i * 8) * HH + n0 + tx];
    __syncthreads();
#pragma unroll
    for (int i = 0; i < 4; i++) {
        const int n = n0 + ty + i * 8, k = k0 + tx;
        const float v = t[tx][ty + i * 8];
        const __nv_bfloat16 hi = __float2bfloat16(v);
        const float lo = v - __bfloat162float(hi);
        g_w1hiT[(size_t)n * DIN + k] = hi;
        g_w1loT[(size_t)n * DIN + k] = __float2bfloat16(lo);
    }
}

// ---------------- K1: v2 = W2 @ w_deep, c = b2 . w_deep ----------------
__global__ void k_prep(const float* __restrict__ W2,
                       const float* __restrict__ w_deep,
                       const float* __restrict__ b2) {
    int h = blockIdx.x * blockDim.x + threadIdx.x;
    if (h < HH) {
        float acc = 0.f;
        const float* row = W2 + (size_t)h * DOUTT;
#pragma unroll 8
        for (int d = 0; d < DOUTT; d++) acc = fmaf(row[d], w_deep[d], acc);
        g_v2[h] = acc;
    }
    if (blockIdx.x == 0 && threadIdx.x == 0) {
        float c = 0.f;
        for (int d = 0; d < DOUTT; d++) c = fmaf(b2[d], w_deep[d], c);
        g_c = c;
    }
}

// ---------------- K2: split-bf16 mma.sync MLP; d1 split fused into nc==0 ----------------
// 256 threads = 8 warps (4m x 2n), warp tile 32x64, BM=128, BN=128, KC=32.
// Word-offset layout (unchanged from round 10/12):
#define T_AH   0
#define T_AL   2560
#define T_BH   5120
#define T_BL   7680
#define BUFW   10240
#define ST_F32 10240     // fp32 stage overlays buf1's A region (4608 <= 5120 words)
#define W_B1S  20480
#define W_V2S  21504
#define W_RED  22528
#define W_US   23552
#define MLP_SMEM_BYTES ((23552 + 192) * 4)

// full load (A bf16 + B bf16), used for nc >= 1
__device__ __forceinline__ void mlp_load(uint32_t sb, uint32_t bufw,
                                         int mbase, int kbase, int nbase, int tid) {
#pragma unroll
    for (int c = 0; c < 2; c++) {
        const int id = c * 256 + tid;
        const int row = id >> 2, col = id & 3;
        const uint32_t w = bufw + row * 20 + col * 4;
        const size_t asrc = (size_t)(mbase + row) * DIN + kbase + col * 8;
        const size_t bsrc = (size_t)(nbase + row) * DIN + kbase + col * 8;
        cp16(sb + (T_AH + w) * 4, (const char*)g_d1hi + asrc * 2);
        cp16(sb + (T_AL + w) * 4, (const char*)g_d1lo + asrc * 2);
        cp16(sb + (T_BH + w) * 4, (const char*)g_w1hiT + bsrc * 2);
        cp16(sb + (T_BL + w) * 4, (const char*)g_w1loT + bsrc * 2);
    }
}

// nc==0 loads: fp32 A chunk -> stage, B bf16 -> given buffer
__device__ __forceinline__ void load_a_f32(uint32_t sb, const float* __restrict__ d1,
                                           int mbase, int kbase, int tid) {
#pragma unroll
    for (int c = 0; c < 4; c++) {
        const int id = c * 256 + tid;
        const int row = id >> 3, cc = id & 7;
        cp16(sb + (ST_F32 + row * 36 + cc * 4) * 4,
             &d1[(size_t)(mbase + row) * DIN + kbase + cc * 4]);
    }
}
__device__ __forceinline__ void load_b(uint32_t sb, uint32_t bufw,
                                       int kbase, int nbase, int tid) {
#pragma unroll
    for (int c = 0; c < 2; c++) {
        const int id = c * 256 + tid;
        const int row = id >> 2, col = id & 3;
        const uint32_t w = bufw + row * 20 + col * 4;
        const size_t bsrc = (size_t)(nbase + row) * DIN + kbase + col * 8;
        cp16(sb + (T_BH + w) * 4, (const char*)g_w1hiT + bsrc * 2);
        cp16(sb + (T_BL + w) * 4, (const char*)g_w1loT + bsrc * 2);
    }
}

// one KC=32 chunk of MMAs (3-term split), addresses precomputed by caller
__device__ __forceinline__ void mma_chunk(uint32_t Ahi, uint32_t Alo,
                                          uint32_t Bhi, uint32_t Blo,
                                          float c[2][8][4]) {
#pragma unroll
    for (int ks = 0; ks < 2; ks++) {
        const uint32_t ko = (uint32_t)ks * 32;   // 8 words
        uint32_t ah[2][4], al[2][4], bb[4][4];
        ldm_x4(ah[0], Ahi + ko);
        ldm_x4(ah[1], Ahi + 1280 + ko);          // +16 rows = 320 words
        ldm_x4(al[0], Alo + ko);
        ldm_x4(al[1], Alo + 1280 + ko);
#pragma unroll
        for (int p = 0; p < 4; p++)
            ldm_x4(bb[p], Bhi + (uint32_t)p * 1280 + ko);
#pragma unroll
        for (int mt = 0; mt < 2; mt++)
#pragma unroll
            for (int p = 0; p < 4; p++) {
                mma_bf16(c[mt][2 * p],     ah[mt], &bb[p][0]);   // hi*hi
                mma_bf16(c[mt][2 * p + 1], ah[mt], &bb[p][2]);
                mma_bf16(c[mt][2 * p],     al[mt], &bb[p][0]);   // lo*hi
                mma_bf16(c[mt][2 * p + 1], al[mt], &bb[p][2]);
            }
#pragma unroll
        for (int p = 0; p < 4; p++)
            ldm_x4(bb[p], Blo + (uint32_t)p * 1280 + ko);
#pragma unroll
        for (int mt = 0; mt < 2; mt++)
#pragma unroll
            for (int p = 0; p < 4; p++) {
                mma_bf16(c[mt][2 * p],     ah[mt], &bb[p][0]);   // hi*lo
                mma_bf16(c[mt][2 * p + 1], ah[mt], &bb[p][2]);
            }
    }
}

__global__ __launch_bounds__(256, 2)
void k_mlp(const float* __restrict__ d1, const float* __restrict__ b1,
           const float* __restrict__ S) {
    extern __shared__ float smf[];
    uint32_t* smw = (uint32_t*)smf;
    const uint32_t sb = smem_u32(smf);
    const int tid = threadIdx.x, wid = tid >> 5, lane = tid & 31;
    const int wm = wid >> 1, wn = wid & 1;       // warp grid 4 x 2
    const int mbase = blockIdx.x * 128;
    const int lq = lane >> 2, lr = lane & 3;

    float* b1s = smf + W_B1S;
    float* v2s = smf + W_V2S;
    for (int i = tid; i < HH; i += 256) { b1s[i] = b1[i]; v2s[i] = g_v2[i]; }
    __syncthreads();

    const int l8 = lane & 7, g = lane >> 3;
    const uint32_t aw = (uint32_t)((wm * 32 + (g & 1) * 8 + l8) * 20 + (g >> 1) * 4);
    const uint32_t bw = (uint32_t)((wn * 64 + (g >> 1) * 8 + l8) * 20 + (g & 1) * 4);
    // convert-phase indices: row = tid>>1, half = tid&1 (16 floats each)
    const int cr = tid >> 1, ch = tid & 1;

    float upart[4] = {0.f, 0.f, 0.f, 0.f};

    for (int nc = 0; nc < 8; nc++) {
        const int nbase = nc * 128;
        float c[2][8][4];
#pragma unroll
        for (int mt = 0; mt < 2; mt++)
#pragma unroll
            for (int nt = 0; nt < 8; nt++)
#pragma unroll
                for (int i = 0; i < 4; i++) c[mt][nt][i] = 0.f;

        if (nc == 0) {
            // ---- fused d1-split pass: fp32 A staged, converted once, written back ----
            load_a_f32(sb, d1, mbase, 0, tid);
            load_b(sb, 0, 0, nbase, tid);
            CP_COMMIT();
            for (int kt = 0; kt < 16; kt++) {
                const int cur = kt & 1, nxt = cur ^ 1;
                CP_WAIT0();
                __syncthreads();
                // convert stage -> buf0 A tiles + global writeback (bit-identical split)
                {
                    const float* st = smf + ST_F32 + cr * 36 + ch * 16;
                    uint32_t hw[8], lw[8];
#pragma unroll
                    for (int g4 = 0; g4 < 4; g4++) {
                        const float4 v = *(const float4*)(st + g4 * 4);
                        const uint32_t h0 = cvt2(v.y, v.x);
                        const uint32_t h1 = cvt2(v.w, v.z);
                        const float l0 = v.x - __uint_as_float(h0 << 16);
                        const float l1 = v.y - __uint_as_float(h0 & 0xffff0000u);
                        const float l2 = v.z - __uint_as_float(h1 << 16);
                        const float l3 = v.w - __uint_as_float(h1 & 0xffff0000u);
                        hw[g4 * 2] = h0; hw[g4 * 2 + 1] = h1;
                        lw[g4 * 2] = cvt2(l1, l0); lw[g4 * 2 + 1] = cvt2(l3, l2);
                    }
                    const uint32_t dw = (uint32_t)(cr * 20 + ch * 8);
                    *(uint4*)(smw + T_AH + dw)     = make_uint4(hw[0], hw[1], hw[2], hw[3]);
                    *(uint4*)(smw + T_AH + dw + 4) = make_uint4(hw[4], hw[5], hw[6], hw[7]);
                    *(uint4*)(smw + T_AL + dw)     = make_uint4(lw[0], lw[1], lw[2], lw[3]);
                    *(uint4*)(smw + T_AL + dw + 4) = make_uint4(lw[4], lw[5], lw[6], lw[7]);
                    const size_t goff = (size_t)(mbase + cr) * DIN + kt * 32 + ch * 16;
                    uint4* gh = (uint4*)(g_d1hi + goff);
                    uint4* gl = (uint4*)(g_d1lo + goff);
                    gh[0] = make_uint4(hw[0], hw[1], hw[2], hw[3]);
                    gh[1] = make_uint4(hw[4], hw[5], hw[6], hw[7]);
                    gl[0] = make_uint4(lw[0], lw[1], lw[2], lw[3]);
                    gl[1] = make_uint4(lw[4], lw[5], lw[6], lw[7]);
                }
                __syncthreads();
                if (kt < 15) {
                    load_a_f32(sb, d1, mbase, (kt + 1) * 32, tid);
                    load_b(sb, nxt * BUFW, (kt + 1) * 32, nbase, tid);
                    CP_COMMIT();
                }
                // A always in buf0; B in cur buffer
                const uint32_t bufb = (uint32_t)cur * (BUFW * 4);
                mma_chunk(sb + (T_AH + aw) * 4, sb + (T_AL + aw) * 4,
                          sb + bufb + (T_BH + bw) * 4, sb + bufb + (T_BL + bw) * 4, c);
            }
        } else {
            // ---- proven round-10 path: bf16 A/B double-buffered ----
            mlp_load(sb, 0, mbase, 0, nbase, tid);
            CP_COMMIT();
            for (int kt = 0; kt < 16; kt++) {
                const int cur = kt & 1, nxt = cur ^ 1;
                CP_WAIT0();
                __syncthreads();
                if (kt < 15) {
                    mlp_load(sb, nxt * BUFW, mbase, (kt + 1) * 32, nbase, tid);
                    CP_COMMIT();
                }
                const uint32_t bufb = (uint32_t)cur * (BUFW * 4);
                mma_chunk(sb + bufb + (T_AH + aw) * 4, sb + bufb + (T_AL + aw) * 4,
                          sb + bufb + (T_BH + bw) * 4, sb + bufb + (T_BL + bw) * 4, c);
            }
        }
        // fused epilogue: upart += relu(c + b1) . v2
#pragma unroll
        for (int mt = 0; mt < 2; mt++)
#pragma unroll
            for (int nt = 0; nt < 8; nt++) {
                const int col0 = nbase + wn * 64 + nt * 8 + 2 * lr;
                const float b1a = b1s[col0], b1b = b1s[col0 + 1];
                const float v2a = v2s[col0], v2b = v2s[col0 + 1];
                upart[0 + mt * 2] = fmaf(fmaxf(c[mt][nt][0] + b1a, 0.f), v2a, upart[0 + mt * 2]);
                upart[0 + mt * 2] = fmaf(fmaxf(c[mt][nt][1] + b1b, 0.f), v2b, upart[0 + mt * 2]);
                upart[1 + mt * 2] = fmaf(fmaxf(c[mt][nt][2] + b1a, 0.f), v2a, upart[1 + mt * 2]);
                upart[1 + mt * 2] = fmaf(fmaxf(c[mt][nt][3] + b1b, 0.f), v2b, upart[1 + mt * 2]);
            }
        __syncthreads();  // before next nc overwrites buffers
    }

    // reduce 8 column-partials per row (deterministic), store u, then y partial
    float* red = smf + W_RED;   // [128][8]
    float* us  = smf + W_US;    // [128]
#pragma unroll
    for (int mt = 0; mt < 2; mt++)
#pragma unroll
        for (int hh = 0; hh < 2; hh++) {
            const int row = wm * 32 + mt * 16 + hh * 8 + lq;
            red[row * 8 + wn * 4 + lr] = upart[mt * 2 + hh];
        }
    __syncthreads();
    if (tid < 128) {
        float s = 0.f;
#pragma unroll
        for (int t = 0; t < 8; t++) s += red[tid * 8 + t];
        const float u = s + g_c;
        g_u[mbase + tid] = u;
        us[tid] = u;
    }
    __syncthreads();
    if (tid < 128) {
        float acc = 0.f;
#pragma unroll 8
        for (int r = 0; r < 128; r++)
            acc = fmaf(S[(size_t)(mbase + r) * SS + tid], us[r], acc);
        g_y_part[blockIdx.x * 128 + tid] = acc;
    }
}

// ---------------- K3: Gram partials (FFMA), 512 CTAs x 128 rows ----------------
__global__ __launch_bounds__(256) void k_gram(const float* __restrict__ Smat) {
    __shared__ __align__(16) float Srow[8][128];
    const int tid = threadIdx.x;
    const int tx = tid & 15, ty = tid >> 4;
    const int i0 = ty * 8, j0 = tx * 8;
    const int base = blockIdx.x * 128;
    const int lr = tid >> 5;
    const int lc = (tid & 31) * 4;

    float acc[8][8];
#pragma unroll
    for (int i = 0; i < 8; i++)
#pragma unroll
        for (int j = 0; j < 8; j++) acc[i][j] = 0.f;

    for (int st = 0; st < 16; st++) {
        __syncthreads();
        *(float4*)&Srow[lr][lc] = *(const float4*)&Smat[(size_t)(base + st * 8 + lr) * SS + lc];
        __syncthreads();
#pragma unroll
        for (int r = 0; r < 8; r++) {
            float a[8], b[8];
            *(float4*)&a[0] = *(float4*)&Srow[r][i0];
            *(float4*)&a[4] = *(float4*)&Srow[r][i0 + 4];
            *(float4*)&b[0] = *(float4*)&Srow[r][j0];
            *(float4*)&b[4] = *(float4*)&Srow[r][j0 + 4];
#pragma unroll
            for (int i = 0; i < 8; i++)
#pragma unroll
                for (int j = 0; j < 8; j++)
                    acc[i][j] = fmaf(a[i], b[j], acc[i][j]);
        }
    }
    float* outp = g_gram_part + (size_t)blockIdx.x * 128 * 128;
#pragma unroll
    for (int i = 0; i < 8; i++)
#pragma unroll
        for (int j = 0; j < 8; j++)
            outp[(i0 + i) * 128 + (j0 + j)] = acc[i][j];
}

// ---------------- K4: reduce partials, 4 threads per output (fixed-order tree) ----------------
__global__ __launch_bounds__(256) void k_reduce() {
    __shared__ float p[256];
    const int tid = threadIdx.x;
    const int il = tid >> 2;
    const int part = tid & 3;
    const int idx = blockIdx.x * 64 + il;

    {   // Gram: 512 partials -> 4 chunks of 128, combined in fixed order
        float s = 0.f;
        const int b0 = part * 128;
        for (int b = 0; b < 128; b++)
            s += g_gram_part[(size_t)(b0 + b) * 16384 + idx];
        p[tid] = s;
    }
    __syncthreads();
    if (part == 0)
        g_G[idx] = p[il * 4] + p[il * 4 + 1] + p[il * 4 + 2] + p[il * 4 + 3];
    __syncthreads();
    if (blockIdx.x == 0) {
        const int j = tid >> 1;
        const int half = tid & 1;
        float s = 0.f;
        const int b0 = half * 256;
        for (int b = 0; b < 256; b++)
            s += g_y_part[(b0 + b) * 128 + j];
        p[tid] = s;
        __syncthreads();
        if (half == 0) g_y[j] = p[j * 2] + p[j * 2 + 1];
    }
}

// ---------------- K5: Richardson solve G z = y ----------------
__global__ void k_solve(const float* __restrict__ w_struct) {
    __shared__ float zs[128];
    const int i = threadIdx.x;
    const float invN = 1.0f / (float)NN;
    const float yi = g_y[i];
    zs[i] = yi * invN;
    __syncthreads();
    for (int it = 0; it < 30; it++) {
        float gz = 0.f;
        const float* Gi = g_G + i * 128;
#pragma unroll 8
        for (int j = 0; j < 128; j++) gz = fmaf(Gi[j], zs[j], gz);
        const float znew = zs[i] + (yi - gz) * invN;
        __syncthreads();
        zs[i] = znew;
        __syncthreads();
    }
    g_wprime[i] = w_struct[i] - zs[i];
}

// ---------------- K6: out[n] = u[n] + S[n,:] . wprime ----------------
__global__ __launch_bounds__(256) void k_final(const float* __restrict__ Smat,
                                               float* __restrict__ out) {
    __shared__ float wp[128];
    const int tid = threadIdx.x;
    if (tid < 128) wp[tid] = g_wprime[tid];
    __syncthreads();
    const int warp = tid >> 5, lane = tid & 31;
    const int row = blockIdx.x * 8 + warp;
    const float4 a = *(const float4*)&Smat[(size_t)row * SS + lane * 4];
    const float4 w = *(const float4*)&wp[lane * 4];
    float s = a.x * w.x + a.y * w.y + a.z * w.z + a.w * w.w;
#pragma unroll
    for (int off = 16; off; off >>= 1) s += __shfl_xor_sync(0xffffffffu, s, off);
    if (lane == 0) out[row] = g_u[row] + s;
}

// ---------------- launch ----------------
extern "C" void kernel_launch(void* const* d_in, const int* in_sizes, int n_in,
                              void* d_out, int out_size) {
    const float* structured = (const float*)d_in[0];
    const float* d1         = (const float*)d_in[1];
    const float* W1         = (const float*)d_in[2];
    const float* b1         = (const float*)d_in[3];
    const float* W2         = (const float*)d_in[4];
    const float* b2         = (const float*)d_in[5];
    const float* w_struct   = (const float*)d_in[6];
    const float* w_deep     = (const float*)d_in[7];
    float* out = (float*)d_out;
    (void)in_sizes; (void)n_in; (void)out_size;

    cudaFuncSetAttribute(k_mlp, cudaFuncAttributeMaxDynamicSharedMemorySize, MLP_SMEM_BYTES);

    k_prep    <<<4, 256>>>(W2, w_deep, b2);
    k_split_w1<<<dim3(32, 16), dim3(32, 8)>>>(W1);
    k_mlp     <<<NN / 128, 256, MLP_SMEM_BYTES>>>(d1, b1, structured);
    k_gram    <<<512, 256>>>(structured);
    k_reduce  <<<256, 256>>>();
    k_solve   <<<1, 128>>>(w_struct);
    k_final   <<<NN / 8, 256>>>(structured, out);
}

// round 15
// speedup vs baseline: 1.5177x; 1.5177x over previous
#include <cuda_runtime.h>
#include <cuda_bf16.h>
#include <cuda_fp16.h>
#include <cstdint>

#define NN   65536
#define SS   128
#define DIN  512
#define HH   1024
#define DOUTT 256

// ---------------- static device scratch ----------------
__device__ float g_u[NN];
__device__ float g_v2[HH];
__device__ float g_c;
__device__ float g_gram_part[512 * 128 * 128];
__device__ float g_y_part[512 * 128];
__device__ float g_G[128 * 128];
__device__ float g_y[128];
__device__ float g_wprime[128];
__device__ __half g_w1T[(size_t)HH * DIN];   // W1^T in fp16, [n][k]

// ---------------- helpers (baseline PTX only — must compile for plain sm_103) ----------------
__device__ __forceinline__ uint32_t smem_u32(const void* p) {
    uint32_t a;
    asm("{ .reg .u64 t; cvta.to.shared.u64 t, %1; cvt.u32.u64 %0, t; }" : "=r"(a) : "l"(p));
    return a;
}
__device__ __forceinline__ void cp16(uint32_t dst, const void* src) {
    asm volatile("cp.async.cg.shared.global [%0], [%1], 16;" :: "r"(dst), "l"(src));
}
#define CP_COMMIT() asm volatile("cp.async.commit_group;" ::: "memory")
#define CP_WAIT0()  asm volatile("cp.async.wait_group 0;" ::: "memory")

__device__ __forceinline__ void mma_f16(float* c, const uint32_t* a, const uint32_t* b) {
    asm volatile("mma.sync.aligned.m16n8k16.row.col.f32.f16.f16.f32 "
        "{%0,%1,%2,%3}, {%4,%5,%6,%7}, {%8,%9}, {%0,%1,%2,%3};"
        : "+f"(c[0]), "+f"(c[1]), "+f"(c[2]), "+f"(c[3])
        : "r"(a[0]), "r"(a[1]), "r"(a[2]), "r"(a[3]), "r"(b[0]), "r"(b[1]));
}
__device__ __forceinline__ void ldm_x4(uint32_t* r, uint32_t addr) {
    asm volatile("ldmatrix.sync.aligned.m8n8.x4.shared.b16 {%0,%1,%2,%3}, [%4];"
        : "=r"(r[0]), "=r"(r[1]), "=r"(r[2]), "=r"(r[3]) : "r"(addr));
}
// pack two fp32 -> fp16x2 word (rn); %1 -> high half, %2 -> low half
__device__ __forceinline__ uint32_t cvt2h(float hi, float lo) {
    uint32_t r;
    asm("cvt.rn.f16x2.f32 %0, %1, %2;" : "=r"(r) : "f"(hi), "f"(lo));
    return r;
}

// ---------------- K0: W1 -> transposed fp16 [n][k] ----------------
__global__ void k_cvt_w1(const float* __restrict__ W1) {
    __shared__ float t[32][33];
    const int tx = threadIdx.x, ty = threadIdx.y;       // 32 x 8
    const int n0 = blockIdx.x * 32, k0 = blockIdx.y * 32;
#pragma unroll
    for (int i = 0; i < 4; i++)
        t[ty + i * 8][tx] = W1[(size_t)(k0 + ty + i * 8) * HH + n0 + tx];
    __syncthreads();
#pragma unroll
    for (int i = 0; i < 4; i++) {
        const int n = n0 + ty + i * 8, k = k0 + tx;
        g_w1T[(size_t)n * DIN + k] = __float2half_rn(t[tx][ty + i * 8]);
    }
}

// ---------------- K1: v2 = W2 @ w_deep, c = b2 . w_deep ----------------
__global__ void k_prep(const float* __restrict__ W2,
                       const float* __restrict__ w_deep,
                       const float* __restrict__ b2) {
    int h = blockIdx.x * blockDim.x + threadIdx.x;
    if (h < HH) {
        float acc = 0.f;
        const float* row = W2 + (size_t)h * DOUTT;
#pragma unroll 8
        for (int d = 0; d < DOUTT; d++) acc = fmaf(row[d], w_deep[d], acc);
        g_v2[h] = acc;
    }
    if (blockIdx.x == 0 && threadIdx.x == 0) {
        float c = 0.f;
        for (int d = 0; d < DOUTT; d++) c = fmaf(b2[d], w_deep[d], c);
        g_c = c;
    }
}

// ---------------- K2: single-term fp16 mma.sync MLP, fused u/y ----------------
// 256 threads = 8 warps (4m x 2n), warp tile 32x64, BM=128, BN=128, KC=32.
// A: fp32 tiles via cp.async (stride 40 words = 32 data + 8 pad; conflict-free
// float2 fragment loads), converted to fp16 fragments in registers.
// B: fp16 W1^T tiles (stride 20 words), ldmatrix.
// Word offsets:
#define T_A0   0
#define T_A1   5120
#define T_B0   10240
#define T_B1   12800
#define W_B1S  15360
#define W_V2S  16384
#define W_RED  17408
#define W_US   18432
#define MLP_SMEM_BYTES ((18432 + 192) * 4)

__device__ __forceinline__ void mlp_load(uint32_t sb, uint32_t abuf, uint32_t bbuf,
                                         const float* __restrict__ d1,
                                         int mbase, int kbase, int nbase, int tid) {
    // A fp32: 128 rows x 32 floats = 1024 16B chunks -> 4/thread
#pragma unroll
    for (int c = 0; c < 4; c++) {
        const int id = c * 256 + tid;
        const int row = id >> 3, cc = id & 7;
        cp16(sb + (abuf + row * 40 + cc * 4) * 4,
             &d1[(size_t)(mbase + row) * DIN + kbase + cc * 4]);
    }
    // B fp16: 128 rows x 32 halves = 512 16B chunks -> 2/thread
#pragma unroll
    for (int c = 0; c < 2; c++) {
        const int id = c * 256 + tid;
        const int row = id >> 2, col = id & 3;
        cp16(sb + (bbuf + row * 20 + col * 4) * 4,
             (const char*)g_w1T + ((size_t)(nbase + row) * DIN + kbase + col * 8) * 2);
    }
}

__global__ __launch_bounds__(256, 2)
void k_mlp(const float* __restrict__ d1, const float* __restrict__ b1,
           const float* __restrict__ S) {
    extern __shared__ float smf[];
    const uint32_t sb = smem_u32(smf);
    const int tid = threadIdx.x, wid = tid >> 5, lane = tid & 31;
    const int wm = wid >> 1, wn = wid & 1;       // warp grid 4 x 2
    const int mbase = blockIdx.x * 128;
    const int lq = lane >> 2, lr = lane & 3;

    float* b1s = smf + W_B1S;
    float* v2s = smf + W_V2S;
    for (int i = tid; i < HH; i += 256) { b1s[i] = b1[i]; v2s[i] = g_v2[i]; }
    __syncthreads();

    // ldmatrix B per-lane address (word offset within a B tile, stride 20)
    const int l8 = lane & 7, g = lane >> 3;
    const uint32_t bw = (uint32_t)((wn * 64 + (g >> 1) * 8 + l8) * 20 + (g & 1) * 4);
    const uint32_t aoff[2] = {T_A0, T_A1};
    const uint32_t boff[2] = {T_B0, T_B1};

    float upart[4] = {0.f, 0.f, 0.f, 0.f};

    for (int nc = 0; nc < 8; nc++) {
        const int nbase = nc * 128;
        float c[2][8][4];
#pragma unroll
        for (int mt = 0; mt < 2; mt++)
#pragma unroll
            for (int nt = 0; nt < 8; nt++)
#pragma unroll
                for (int i = 0; i < 4; i++) c[mt][nt][i] = 0.f;

        mlp_load(sb, aoff[0], boff[0], d1, mbase, 0, nbase, tid);
        CP_COMMIT();

        for (int kt = 0; kt < 16; kt++) {
            const int cur = kt & 1, nxt = cur ^ 1;
            CP_WAIT0();
            __syncthreads();
            if (kt < 15) {
                mlp_load(sb, aoff[nxt], boff[nxt], d1, mbase, (kt + 1) * 32, nbase, tid);
                CP_COMMIT();
            }
            const float* As = smf + aoff[cur];
            const uint32_t Bb = sb + (boff[cur] + bw) * 4;
#pragma unroll
            for (int ks = 0; ks < 2; ks++) {
                // A fragments: fp32 -> fp16 in registers
                uint32_t ah[2][4];
#pragma unroll
                for (int mt = 0; mt < 2; mt++) {
                    const float* ap = As + (wm * 32 + mt * 16 + lq) * 40 + ks * 16 + 2 * lr;
                    const float2 v0 = *(const float2*)(ap);          // row, k0
                    const float2 v1 = *(const float2*)(ap + 8);      // row, k+8
                    const float2 v2 = *(const float2*)(ap + 8 * 40); // row+8, k0
                    const float2 v3 = *(const float2*)(ap + 8 * 40 + 8);
                    ah[mt][0] = cvt2h(v0.y, v0.x);
                    ah[mt][1] = cvt2h(v2.y, v2.x);
                    ah[mt][2] = cvt2h(v1.y, v1.x);
                    ah[mt][3] = cvt2h(v3.y, v3.x);
                }
                uint32_t bb[4][4];
                const uint32_t ko = (uint32_t)ks * 32;   // 16 halves = 32 bytes
#pragma unroll
                for (int p = 0; p < 4; p++)
                    ldm_x4(bb[p], Bb + (uint32_t)p * 1280 + ko);
#pragma unroll
                for (int mt = 0; mt < 2; mt++)
#pragma unroll
                    for (int p = 0; p < 4; p++) {
                        mma_f16(c[mt][2 * p],     ah[mt], &bb[p][0]);
                        mma_f16(c[mt][2 * p + 1], ah[mt], &bb[p][2]);
                    }
            }
        }
        // fused epilogue: upart += relu(c + b1) . v2
#pragma unroll
        for (int mt = 0; mt < 2; mt++)
#pragma unroll
            for (int nt = 0; nt < 8; nt++) {
                const int col0 = nbase + wn * 64 + nt * 8 + 2 * lr;
                const float b1a = b1s[col0], b1b = b1s[col0 + 1];
                const float v2a = v2s[col0], v2b = v2s[col0 + 1];
                upart[0 + mt * 2] = fmaf(fmaxf(c[mt][nt][0] + b1a, 0.f), v2a, upart[0 + mt * 2]);
                upart[0 + mt * 2] = fmaf(fmaxf(c[mt][nt][1] + b1b, 0.f), v2b, upart[0 + mt * 2]);
                upart[1 + mt * 2] = fmaf(fmaxf(c[mt][nt][2] + b1a, 0.f), v2a, upart[1 + mt * 2]);
                upart[1 + mt * 2] = fmaf(fmaxf(c[mt][nt][3] + b1b, 0.f), v2b, upart[1 + mt * 2]);
            }
        __syncthreads();  // before next nc overwrites buffers
    }

    // reduce 8 column-partials per row (deterministic), store u, then y partial
    float* red = smf + W_RED;   // [128][8]
    float* us  = smf + W_US;    // [128]
#pragma unroll
    for (int mt = 0; mt < 2; mt++)
#pragma unroll
        for (int hh = 0; hh < 2; hh++) {
            const int row = wm * 32 + mt * 16 + hh * 8 + lq;
            red[row * 8 + wn * 4 + lr] = upart[mt * 2 + hh];
        }
    __syncthreads();
    if (tid < 128) {
        float s = 0.f;
#pragma unroll
        for (int t = 0; t < 8; t++) s += red[tid * 8 + t];
        const float u = s + g_c;
        g_u[mbase + tid] = u;
        us[tid] = u;
    }
    __syncthreads();
    if (tid < 128) {
        float acc = 0.f;
#pragma unroll 8
        for (int r = 0; r < 128; r++)
            acc = fmaf(S[(size_t)(mbase + r) * SS + tid], us[r], acc);
        g_y_part[blockIdx.x * 128 + tid] = acc;
    }
}

// ---------------- K3: Gram partials (FFMA), 512 CTAs x 128 rows ----------------
__global__ __launch_bounds__(256) void k_gram(const float* __restrict__ Smat) {
    __shared__ __align__(16) float Srow[8][128];
    const int tid = threadIdx.x;
    const int tx = tid & 15, ty = tid >> 4;
    const int i0 = ty * 8, j0 = tx * 8;
    const int base = blockIdx.x * 128;
    const int lr = tid >> 5;
    const int lc = (tid & 31) * 4;

    float acc[8][8];
#pragma unroll
    for (int i = 0; i < 8; i++)
#pragma unroll
        for (int j = 0; j < 8; j++) acc[i][j] = 0.f;

    for (int st = 0; st < 16; st++) {
        __syncthreads();
        *(float4*)&Srow[lr][lc] = *(const float4*)&Smat[(size_t)(base + st * 8 + lr) * SS + lc];
        __syncthreads();
#pragma unroll
        for (int r = 0; r < 8; r++) {
            float a[8], b[8];
            *(float4*)&a[0] = *(float4*)&Srow[r][i0];
            *(float4*)&a[4] = *(float4*)&Srow[r][i0 + 4];
            *(float4*)&b[0] = *(float4*)&Srow[r][j0];
            *(float4*)&b[4] = *(float4*)&Srow[r][j0 + 4];
#pragma unroll
            for (int i = 0; i < 8; i++)
#pragma unroll
                for (int j = 0; j < 8; j++)
                    acc[i][j] = fmaf(a[i], b[j], acc[i][j]);
        }
    }
    float* outp = g_gram_part + (size_t)blockIdx.x * 128 * 128;
#pragma unroll
    for (int i = 0; i < 8; i++)
#pragma unroll
        for (int j = 0; j < 8; j++)
            outp[(i0 + i) * 128 + (j0 + j)] = acc[i][j];
}

// ---------------- K4: reduce partials, 4 threads per output (fixed-order tree) ----------------
__global__ __launch_bounds__(256) void k_reduce() {
    __shared__ float p[256];
    const int tid = threadIdx.x;
    const int il = tid >> 2;
    const int part = tid & 3;
    const int idx = blockIdx.x * 64 + il;

    {   // Gram: 512 partials -> 4 chunks of 128, combined in fixed order
        float s = 0.f;
        const int b0 = part * 128;
        for (int b = 0; b < 128; b++)
            s += g_gram_part[(size_t)(b0 + b) * 16384 + idx];
        p[tid] = s;
    }
    __syncthreads();
    if (part == 0)
        g_G[idx] = p[il * 4] + p[il * 4 + 1] + p[il * 4 + 2] + p[il * 4 + 3];
    __syncthreads();
    if (blockIdx.x == 0) {
        const int j = tid >> 1;
        const int half = tid & 1;
        float s = 0.f;
        const int b0 = half * 256;
        for (int b = 0; b < 256; b++)
            s += g_y_part[(b0 + b) * 128 + j];
        p[tid] = s;
        __syncthreads();
        if (half == 0) g_y[j] = p[j * 2] + p[j * 2 + 1];
    }
}

// ---------------- K5: Richardson solve G z = y ----------------
__global__ void k_solve(const float* __restrict__ w_struct) {
    __shared__ float zs[128];
    const int i = threadIdx.x;
    const float invN = 1.0f / (float)NN;
    const float yi = g_y[i];
    zs[i] = yi * invN;
    __syncthreads();
    for (int it = 0; it < 30; it++) {
        float gz = 0.f;
        const float* Gi = g_G + i * 128;
#pragma unroll 8
        for (int j = 0; j < 128; j++) gz = fmaf(Gi[j], zs[j], gz);
        const float znew = zs[i] + (yi - gz) * invN;
        __syncthreads();
        zs[i] = znew;
        __syncthreads();
    }
    g_wprime[i] = w_struct[i] - zs[i];
}

// ---------------- K6: out[n] = u[n] + S[n,:] . wprime ----------------
__global__ __launch_bounds__(256) void k_final(const float* __restrict__ Smat,
                                               float* __restrict__ out) {
    __shared__ float wp[128];
    const int tid = threadIdx.x;
    if (tid < 128) wp[tid] = g_wprime[tid];
    __syncthreads();
    const int warp = tid >> 5, lane = tid & 31;
    const int row = blockIdx.x * 8 + warp;
    const float4 a = *(const float4*)&Smat[(size_t)row * SS + lane * 4];
    const float4 w = *(const float4*)&wp[lane * 4];
    float s = a.x * w.x + a.y * w.y + a.z * w.z + a.w * w.w;
#pragma unroll
    for (int off = 16; off; off >>= 1) s += __shfl_xor_sync(0xffffffffu, s, off);
    if (lane == 0) out[row] = g_u[row] + s;
}

// ---------------- launch ----------------
extern "C" void kernel_launch(void* const* d_in, const int* in_sizes, int n_in,
                              void* d_out, int out_size) {
    const float* structured = (const float*)d_in[0];
    const float* d1         = (const float*)d_in[1];
    const float* W1         = (const float*)d_in[2];
    const float* b1         = (const float*)d_in[3];
    const float* W2         = (const float*)d_in[4];
    const float* b2         = (const float*)d_in[5];
    const float* w_struct   = (const float*)d_in[6];
    const float* w_deep     = (const float*)d_in[7];
    float* out = (float*)d_out;
    (void)in_sizes; (void)n_in; (void)out_size;

    cudaFuncSetAttribute(k_mlp, cudaFuncAttributeMaxDynamicSharedMemorySize, MLP_SMEM_BYTES);

    k_prep  <<<4, 256>>>(W2, w_deep, b2);
    k_cvt_w1<<<dim3(32, 16), dim3(32, 8)>>>(W1);
    k_mlp   <<<NN / 128, 256, MLP_SMEM_BYTES>>>(d1, b1, structured);
    k_gram  <<<512, 256>>>(structured);
    k_reduce<<<256, 256>>>();
    k_solve <<<1, 128>>>(w_struct);
    k_final <<<NN / 8, 256>>>(structured, out);
}